// round 15
// baseline (speedup 1.0000x reference)
#include <cuda_runtime.h>
#include <cuda_fp16.h>
#include <cstdint>

// ---------------------------------------------------------------------------
// B=4, N=2048, D=1024. scores sum over (h,d) -> single-head attn over 1024.
// ALGEBRAIC FOLD: S = x (Wq^T Wk) x^T,  out = P x (Wv^T Wo^T) + b.
//   Wc = [W~^T ; G~^T]  (weight products, 3-term)
//   y = x @ W~  (3-term: feeds softmax logits, precision-critical)
//   U = x @ G~  (2-term: feeds output only, ~2e-4 direct)
//   S[b] = y[b] @ x[b]^T * 0.125 ; P = softmax(S) (fp16 hi)
//   out  = Ph @ U^T_h + b_out   (1-term)
// ---------------------------------------------------------------------------

#define BM 128
#define BN 128
#define BK 32
#define TILE_B 8192u                    // 128 rows * 64 B (32 fp16, no pad)

// ---------------- scratch (device globals: allocation-guard safe) ----------
__device__ __align__(256) float  g_S[4ull * 2048 * 2048];     // 64 MB
__device__ __align__(256) __half g_xh[8192ull * 1024];
__device__ __align__(256) __half g_xl[8192ull * 1024];
__device__ __align__(256) __half g_bAh[2048ull * 1024];       // [Wk^T ; Wo] hi
__device__ __align__(256) __half g_bAl[2048ull * 1024];
__device__ __align__(256) __half g_bBh[2048ull * 1024];       // [Wq^T ; Wv^T] hi
__device__ __align__(256) __half g_bBl[2048ull * 1024];
__device__ __align__(256) __half g_Wch[2048ull * 1024];       // [W~^T ; G~^T] hi
__device__ __align__(256) __half g_Wcl[2048ull * 1024];       // lo
__device__ __align__(256) __half g_yUh[8192ull * 2048];       // [y | U] hi
__device__ __align__(256) __half g_yUl[8192ull * 2048];       // lo (y half only used)
__device__ __align__(256) __half g_Sh[4ull * 2048 * 2048];    // P hi
__device__ __align__(256) __half g_Ut[4ull * 1024 * 2048];    // U^T per batch

// ---------------------------------------------------------------------------
__device__ __forceinline__ uint32_t s2u(const void* p) {
    uint32_t a;
    asm("{ .reg .u64 t; cvta.to.shared.u64 t, %1; cvt.u32.u64 %0, t; }"
        : "=r"(a) : "l"(p));
    return a;
}

__device__ __forceinline__ void cp16(uint32_t dst, const void* src) {
    asm volatile("cp.async.cg.shared.global [%0], [%1], 16;" :: "r"(dst), "l"(src));
}

__device__ __forceinline__ void ldm4(uint32_t* r, uint32_t addr) {
    asm volatile("ldmatrix.sync.aligned.m8n8.x4.shared.b16 {%0,%1,%2,%3}, [%4];"
        : "=r"(r[0]), "=r"(r[1]), "=r"(r[2]), "=r"(r[3]) : "r"(addr));
}

__device__ __forceinline__ void mma_f16(float* c, const uint32_t* a,
                                        uint32_t b0, uint32_t b1) {
    asm volatile(
        "mma.sync.aligned.m16n8k16.row.col.f32.f16.f16.f32 "
        "{%0,%1,%2,%3}, {%4,%5,%6,%7}, {%8,%9}, {%0,%1,%2,%3};"
        : "+f"(c[0]), "+f"(c[1]), "+f"(c[2]), "+f"(c[3])
        : "r"(a[0]), "r"(a[1]), "r"(a[2]), "r"(a[3]), "r"(b0), "r"(b1));
}

__device__ __forceinline__ void split1(float x, __half& h, __half& l) {
    h = __float2half_rn(x);
    l = __float2half_rn(x - __half2float(h));
}

// ---------------------------------------------------------------------------
// fp32 -> (hi, lo) fp16 split, vectorized.
__global__ void __launch_bounds__(256)
split_kernel(const float4* __restrict__ in,
             __half2* __restrict__ h, __half2* __restrict__ l, int n4)
{
    int i = blockIdx.x * blockDim.x + threadIdx.x;
    if (i < n4) {
        float4 v = in[i];
        __half hx, hy, hz, hw, lx, ly, lz, lw;
        split1(v.x, hx, lx); split1(v.y, hy, ly);
        split1(v.z, hz, lz); split1(v.w, hw, lw);
        h[2 * i]     = __halves2half2(hx, hy);
        h[2 * i + 1] = __halves2half2(hz, hw);
        l[2 * i]     = __halves2half2(lx, ly);
        l[2 * i + 1] = __halves2half2(lz, lw);
    }
}

// ---------------------------------------------------------------------------
// Fused fp32 1024x1024 transpose + fp16 split: dsth/dstl[c][r] = split(src[r][c])
__global__ void __launch_bounds__(256)
transpose_split(const float* __restrict__ src,
                __half* __restrict__ dsth, __half* __restrict__ dstl)
{
    __shared__ float t[32][33];
    int r0 = blockIdx.x * 32, c0 = blockIdx.y * 32;
    int tx = threadIdx.x, ty = threadIdx.y;   // 32 x 8
#pragma unroll
    for (int i = 0; i < 32; i += 8)
        t[ty + i][tx] = src[(size_t)(r0 + ty + i) * 1024 + c0 + tx];
    __syncthreads();
#pragma unroll
    for (int i = 0; i < 32; i += 8) {
        float v = t[tx][ty + i];
        __half h, l;
        split1(v, h, l);
        size_t idx = (size_t)(c0 + ty + i) * 1024 + r0 + tx;
        dsth[idx] = h;
        dstl[idx] = l;
    }
}

// ---------------------------------------------------------------------------
// Ut[b][o][m] = yU[b*2048 + m][1024 + o]  (fp16, U = right half of yU)
__global__ void __launch_bounds__(256)
transpose_u(const __half* __restrict__ yU, __half* __restrict__ Ut)
{
    __shared__ __half t[32][34];
    int b  = blockIdx.z;
    int m0 = blockIdx.x * 32;
    int o0 = blockIdx.y * 32;
    int tx = threadIdx.x, ty = threadIdx.y;   // 32 x 8
    const __half* s = yU + (size_t)b * 2048 * 2048 + 1024;
#pragma unroll
    for (int i = 0; i < 32; i += 8)
        t[ty + i][tx] = s[(size_t)(m0 + ty + i) * 2048 + o0 + tx];
    __syncthreads();
    __half* d = Ut + (size_t)b * 1024 * 2048;
#pragma unroll
    for (int i = 0; i < 32; i += 8)
        d[(size_t)(o0 + ty + i) * 2048 + m0 + tx] = t[tx][ty + i];
}

// ---------------------------------------------------------------------------
// Split NT tensor-core GEMM: C = alpha*A B^T (+bias);
// NT=3: Ah·Bh + Ah·Bl + Al·Bh;  NT=2: (Ah+Al)·Bh;  NT=1: Ah·Bh.
// Grid (N/BN, M/BM, batch); 256 threads = 8 warps (2m x 4n), 64x32 per warp.
// Output: fp32 (Cf) or split fp16 (Ch, optional Cl).
// ---------------------------------------------------------------------------
template <int NT>
__global__ void __launch_bounds__(256, 2)
gemm_nt_split(const __half* __restrict__ Ah, const __half* __restrict__ Al,
              const __half* __restrict__ Bh, const __half* __restrict__ Bl,
              float* __restrict__ Cf,
              __half* __restrict__ Ch, __half* __restrict__ Cl,
              const float* __restrict__ bias,
              int lda, int ldb, int ldc, int K, float alpha,
              long long sA, long long sB, long long sC)
{
    extern __shared__ char smem[];
    constexpr uint32_t NTILES = (NT == 3) ? 4u : (NT == 2 ? 3u : 2u);
    constexpr uint32_t STB   = NTILES * TILE_B;
    constexpr uint32_t O_BH  = (NT >= 2) ? 2u * TILE_B : TILE_B;

    const long long offA = (long long)blockIdx.z * sA;
    const long long offB = (long long)blockIdx.z * sB;
    const long long offC = (long long)blockIdx.z * sC;
    Ah += offA; if (NT >= 2) Al += offA;
    Bh += offB; if (NT == 3) Bl += offB;

    const int tid  = threadIdx.x;
    const int wid  = tid >> 5, lane = tid & 31;
    const int wm   = wid & 1,  wn   = wid >> 1;
    const int g    = lane >> 2, t   = lane & 3;
    const int row0 = blockIdx.y * BM;
    const int col0 = blockIdx.x * BN;

    const uint32_t smem_u = s2u(smem);

    const __half* Abh = Ah + (size_t)row0 * lda;
    const __half* Abl = (NT >= 2) ? (Al + (size_t)row0 * lda) : nullptr;
    const __half* Bbh = Bh + (size_t)col0 * ldb;
    const __half* Bbl = (NT == 3) ? (Bl + (size_t)col0 * ldb) : nullptr;

    float acc[4][4][4];
#pragma unroll
    for (int i = 0; i < 4; i++)
#pragma unroll
        for (int j = 0; j < 4; j++)
#pragma unroll
            for (int r = 0; r < 4; r++)
                acc[i][j][r] = 0.0f;

    const int nk = K / BK;

    const int lr = tid >> 2;
    const int lc = tid & 3;

    auto load_tile = [&](int kb, int s) {
        const uint32_t st = smem_u + (uint32_t)s * STB;
        const int kc = kb * BK + lc * 8;
#pragma unroll
        for (int hh = 0; hh < 2; hh++) {
            const int r = lr + hh * 64;
            const uint32_t phys = (uint32_t)(lc ^ ((r >> 1) & 3));
            const uint32_t off  = (uint32_t)(r * 64) + phys * 16u;
            cp16(st + off, Abh + (size_t)r * lda + kc);
            if (NT >= 2)
                cp16(st + TILE_B + off, Abl + (size_t)r * lda + kc);
            cp16(st + O_BH + off, Bbh + (size_t)r * ldb + kc);
            if (NT == 3)
                cp16(st + 3 * TILE_B + off, Bbl + (size_t)r * ldb + kc);
        }
    };

    load_tile(0, 0);
    asm volatile("cp.async.commit_group;");
    load_tile(1, 1);
    asm volatile("cp.async.commit_group;");

    const int lrow  = lane & 15;
    const int khalf = lane >> 4;

    int cur = 0;
    for (int kb = 0; kb < nk; kb++) {
        if (kb + 1 < nk) asm volatile("cp.async.wait_group 1;");
        else             asm volatile("cp.async.wait_group 0;");
        __syncthreads();

        const uint32_t st = smem_u + (uint32_t)cur * STB;

#pragma unroll
        for (int ks = 0; ks < 2; ks++) {
            uint32_t bh[2][4], bl[2][4], af[4][4];
#pragma unroll
            for (int jp = 0; jp < 2; jp++) {
                const int row = wn * 32 + jp * 16 + lrow;
                const uint32_t phys = (uint32_t)((ks * 2 + khalf) ^ ((row >> 1) & 3));
                const uint32_t bd = st + O_BH + (uint32_t)(row * 64) + phys * 16u;
                ldm4(bh[jp], bd);
                if (NT == 3) ldm4(bl[jp], bd + TILE_B);
            }
#pragma unroll
            for (int i = 0; i < 4; i++) {
                const int row = wm * 64 + i * 16 + lrow;
                const uint32_t phys = (uint32_t)((ks * 2 + khalf) ^ ((row >> 1) & 3));
                ldm4(af[i], st + (uint32_t)(row * 64) + phys * 16u);
            }
#pragma unroll
            for (int i = 0; i < 4; i++)
#pragma unroll
                for (int j = 0; j < 4; j++) {
                    const int jp = j >> 1, sjj = j & 1;
                    mma_f16(acc[i][j], af[i], bh[jp][sjj], bh[jp][sjj + 2]);
                }
            if (NT == 3) {
#pragma unroll
                for (int i = 0; i < 4; i++)
#pragma unroll
                    for (int j = 0; j < 4; j++) {
                        const int jp = j >> 1, sjj = j & 1;
                        mma_f16(acc[i][j], af[i], bl[jp][sjj], bl[jp][sjj + 2]);
                    }
            }
            if (NT >= 2) {
#pragma unroll
                for (int i = 0; i < 4; i++) {
                    const int row = wm * 64 + i * 16 + lrow;
                    const uint32_t phys = (uint32_t)((ks * 2 + khalf) ^ ((row >> 1) & 3));
                    ldm4(af[i], st + TILE_B + (uint32_t)(row * 64) + phys * 16u);
                }
#pragma unroll
                for (int i = 0; i < 4; i++)
#pragma unroll
                    for (int j = 0; j < 4; j++) {
                        const int jp = j >> 1, sjj = j & 1;
                        mma_f16(acc[i][j], af[i], bh[jp][sjj], bh[jp][sjj + 2]);
                    }
            }
        }

        if (kb + 2 < nk) {
            const int ls = (cur + 2 >= 3) ? cur - 1 : cur + 2;
            load_tile(kb + 2, ls);
            asm volatile("cp.async.commit_group;");
        }
        cur = (cur + 1 == 3) ? 0 : cur + 1;
    }

    // ---- epilogue
#pragma unroll
    for (int i = 0; i < 4; i++) {
        const int r = row0 + wm * 64 + i * 16 + g;
#pragma unroll
        for (int j = 0; j < 4; j++) {
            const int c = col0 + wn * 32 + j * 8 + 2 * t;
            float v[4];
            v[0] = alpha * acc[i][j][0];
            v[1] = alpha * acc[i][j][1];
            v[2] = alpha * acc[i][j][2];
            v[3] = alpha * acc[i][j][3];
            if (bias) {
                float bx = bias[c], by = bias[c + 1];
                v[0] += bx; v[1] += by; v[2] += bx; v[3] += by;
            }
            if (Cf) {
                *(float2*)(Cf + offC + (size_t)r * ldc + c)       = make_float2(v[0], v[1]);
                *(float2*)(Cf + offC + (size_t)(r + 8) * ldc + c) = make_float2(v[2], v[3]);
            }
            if (Ch) {
                __half h0, l0, h1, l1, h2, l2, h3, l3;
                split1(v[0], h0, l0); split1(v[1], h1, l1);
                split1(v[2], h2, l2); split1(v[3], h3, l3);
                *(__half2*)(Ch + offC + (size_t)r * ldc + c)       = __halves2half2(h0, h1);
                *(__half2*)(Ch + offC + (size_t)(r + 8) * ldc + c) = __halves2half2(h2, h3);
                if (Cl) {
                    *(__half2*)(Cl + offC + (size_t)r * ldc + c)       = __halves2half2(l0, l1);
                    *(__half2*)(Cl + offC + (size_t)(r + 8) * ldc + c) = __halves2half2(l2, l3);
                }
            }
        }
    }
}

// ---------------------------------------------------------------------------
// Row softmax over 2048-wide rows (vectorized); writes fp16 probs (hi only).
__global__ void __launch_bounds__(256)
softmax_fp16(const float4* __restrict__ S4, __half2* __restrict__ Sh2)
{
    const size_t b4 = (size_t)blockIdx.x * 512;
    const int tid = threadIdx.x;

    float4 va = S4[b4 + tid];
    float4 vb = S4[b4 + tid + 256];

    float m = fmaxf(fmaxf(fmaxf(va.x, va.y), fmaxf(va.z, va.w)),
                    fmaxf(fmaxf(vb.x, vb.y), fmaxf(vb.z, vb.w)));

    __shared__ float red[8];
#pragma unroll
    for (int o = 16; o; o >>= 1) m = fmaxf(m, __shfl_xor_sync(0xffffffffu, m, o));
    if ((tid & 31) == 0) red[tid >> 5] = m;
    __syncthreads();
    m = red[0];
#pragma unroll
    for (int i = 1; i < 8; i++) m = fmaxf(m, red[i]);
    __syncthreads();

    va.x = __expf(va.x - m); va.y = __expf(va.y - m);
    va.z = __expf(va.z - m); va.w = __expf(va.w - m);
    vb.x = __expf(vb.x - m); vb.y = __expf(vb.y - m);
    vb.z = __expf(vb.z - m); vb.w = __expf(vb.w - m);
    float s = va.x + va.y + va.z + va.w + vb.x + vb.y + vb.z + vb.w;

#pragma unroll
    for (int o = 16; o; o >>= 1) s += __shfl_xor_sync(0xffffffffu, s, o);
    if ((tid & 31) == 0) red[tid >> 5] = s;
    __syncthreads();
    s = 0.0f;
#pragma unroll
    for (int i = 0; i < 8; i++) s += red[i];

    const float inv = 1.0f / s;
    const size_t h2base = (size_t)blockIdx.x * 1024;

    Sh2[h2base + 2 * tid] =
        __halves2half2(__float2half_rn(va.x * inv), __float2half_rn(va.y * inv));
    Sh2[h2base + 2 * tid + 1] =
        __halves2half2(__float2half_rn(va.z * inv), __float2half_rn(va.w * inv));
    Sh2[h2base + 2 * (tid + 256)] =
        __halves2half2(__float2half_rn(vb.x * inv), __float2half_rn(vb.y * inv));
    Sh2[h2base + 2 * (tid + 256) + 1] =
        __halves2half2(__float2half_rn(vb.z * inv), __float2half_rn(vb.w * inv));
}

// ---------------------------------------------------------------------------
extern "C" void kernel_launch(void* const* d_in, const int* in_sizes, int n_in,
                              void* d_out, int out_size)
{
    (void)in_sizes; (void)n_in; (void)out_size;
    const float* x     = (const float*)d_in[0];   // [4,2048,1024]
    const float* w_qkv = (const float*)d_in[1];   // [3072,1024]
    const float* w_out = (const float*)d_in[2];   // [1024,1024]
    const float* b_out = (const float*)d_in[3];   // [1024]
    float* out = (float*)d_out;                   // [4,2048,1024]

    float* S;
    __half *xh, *xl, *bAh, *bAl, *bBh, *bBl, *Wch, *Wcl, *yUh, *yUl, *Sh, *Ut;
    cudaGetSymbolAddress((void**)&S,    g_S);
    cudaGetSymbolAddress((void**)&xh,   g_xh);   cudaGetSymbolAddress((void**)&xl,   g_xl);
    cudaGetSymbolAddress((void**)&bAh,  g_bAh);  cudaGetSymbolAddress((void**)&bAl,  g_bAl);
    cudaGetSymbolAddress((void**)&bBh,  g_bBh);  cudaGetSymbolAddress((void**)&bBl,  g_bBl);
    cudaGetSymbolAddress((void**)&Wch,  g_Wch);  cudaGetSymbolAddress((void**)&Wcl,  g_Wcl);
    cudaGetSymbolAddress((void**)&yUh,  g_yUh);  cudaGetSymbolAddress((void**)&yUl,  g_yUl);
    cudaGetSymbolAddress((void**)&Sh,   g_Sh);
    cudaGetSymbolAddress((void**)&Ut,   g_Ut);

    const int SM3 = 3 * 4 * TILE_B;   // 98304
    const int SM2 = 3 * 3 * TILE_B;   // 73728
    const int SM1 = 3 * 2 * TILE_B;   // 49152
    cudaFuncSetAttribute(gemm_nt_split<3>,
                         cudaFuncAttributeMaxDynamicSharedMemorySize, SM3);
    cudaFuncSetAttribute(gemm_nt_split<2>,
                         cudaFuncAttributeMaxDynamicSharedMemorySize, SM2);
    cudaFuncSetAttribute(gemm_nt_split<1>,
                         cudaFuncAttributeMaxDynamicSharedMemorySize, SM1);

    // 0) split x; build packed weight operands (fused transpose+split)
    {
        int n4 = 8192 * 1024 / 4;
        split_kernel<<<(n4 + 255) / 256, 256>>>((const float4*)x,
            (__half2*)xh, (__half2*)xl, n4);
    }
    // bA = [Wk^T ; Wo],  bB = [Wq^T ; Wv^T]
    transpose_split<<<dim3(32, 32), dim3(32, 8)>>>(w_qkv + 1024ll * 1024, bAh, bAl);
    {
        int n4 = 1024 * 1024 / 4;   // Wo: no transpose
        split_kernel<<<(n4 + 255) / 256, 256>>>((const float4*)w_out,
            (__half2*)(bAh + 1024ll * 1024), (__half2*)(bAl + 1024ll * 1024), n4);
    }
    transpose_split<<<dim3(32, 32), dim3(32, 8)>>>(w_qkv, bBh, bBl);
    transpose_split<<<dim3(32, 32), dim3(32, 8)>>>(w_qkv + 2048ll * 1024,
                                                   bBh + 1024ll * 1024,
                                                   bBl + 1024ll * 1024);

    // 1) weight products (batched z=2): Wc[0]=W~^T, Wc[1]=G~^T (3-term)
    gemm_nt_split<3><<<dim3(8, 8, 2), 256, SM3>>>(
        bAh, bAl, bBh, bBl, nullptr, Wch, Wcl, nullptr,
        1024, 1024, 1024, 1024, 1.0f,
        1024ll * 1024, 1024ll * 1024, 1024ll * 1024);

    // 2a) y = x @ W~ : M=8192, N=1024, K=1024 (3-term; logits-critical)
    gemm_nt_split<3><<<dim3(8, 64, 1), 256, SM3>>>(
        xh, xl, Wch, Wcl, nullptr, yUh, yUl, nullptr,
        1024, 1024, 2048, 1024, 1.0f, 0, 0, 0);

    // 2b) U = x @ G~ : M=8192, N=1024, K=1024 (2-term; hi-only output)
    gemm_nt_split<2><<<dim3(8, 64, 1), 256, SM2>>>(
        xh, xl, Wch + 1024ll * 1024, nullptr, nullptr,
        yUh + 1024, nullptr, nullptr,
        1024, 1024, 2048, 1024, 1.0f, 0, 0, 0);

    // 3) S[b] = y[b] @ x[b]^T * 0.125 : fp32 out (3-term)
    gemm_nt_split<3><<<dim3(16, 16, 4), 256, SM3>>>(
        yUh, yUl, xh, xl, S, nullptr, nullptr, nullptr,
        2048, 1024, 2048, 1024, 0.125f,
        2048ll * 2048, 2048ll * 1024, 2048ll * 2048);

    // 4) softmax -> fp16 probs (hi only)
    softmax_fp16<<<4 * 2048, 256>>>((const float4*)S, (__half2*)Sh);

    // 5) Ut[b] = U[b]^T
    transpose_u<<<dim3(64, 32, 4), dim3(32, 8)>>>(yUh, Ut);

    // 6) out = Ph @ U + b_out : M=2048, N=1024, K=2048 (1-term)
    gemm_nt_split<1><<<dim3(8, 16, 4), 256, SM1>>>(
        Sh, nullptr, Ut, nullptr, out, nullptr, nullptr, b_out,
        2048, 2048, 1024, 2048, 1.0f,
        2048ll * 2048, 1024ll * 2048, 2048ll * 1024);
}

// round 16
// speedup vs baseline: 1.0063x; 1.0063x over previous
#include <cuda_runtime.h>
#include <cuda_fp16.h>
#include <cstdint>

// ---------------------------------------------------------------------------
// B=4, N=2048, D=1024. scores sum over (h,d) -> single-head attn over 1024.
// ALGEBRAIC FOLD: S = x (Wq^T Wk) x^T,  out = P x (Wv^T Wo^T) + b.
//   Wc = [W~^T ; G~^T]  (weight products, 3-term)
//   [y|U] = x @ Wc^T    (ONE launch; y-half CTAs 3-term, U-half CTAs 2-term)
//   S[b] = y[b] @ x[b]^T * 0.125 ; P = softmax(S) (fp16 hi)
//   out  = Ph @ U^T_h + b_out   (1-term)
// ---------------------------------------------------------------------------

#define BM 128
#define BN 128
#define BK 32
#define TILE_B 8192u                    // 128 rows * 64 B (32 fp16, no pad)

// ---------------- scratch (device globals: allocation-guard safe) ----------
__device__ __align__(256) float  g_S[4ull * 2048 * 2048];     // 64 MB
__device__ __align__(256) __half g_xh[8192ull * 1024];
__device__ __align__(256) __half g_xl[8192ull * 1024];
__device__ __align__(256) __half g_bAh[2048ull * 1024];       // [Wk^T ; Wo] hi
__device__ __align__(256) __half g_bAl[2048ull * 1024];
__device__ __align__(256) __half g_bBh[2048ull * 1024];       // [Wq^T ; Wv^T] hi
__device__ __align__(256) __half g_bBl[2048ull * 1024];
__device__ __align__(256) __half g_Wch[2048ull * 1024];       // [W~^T ; G~^T] hi
__device__ __align__(256) __half g_Wcl[2048ull * 1024];       // lo
__device__ __align__(256) __half g_yUh[8192ull * 2048];       // [y | U] hi
__device__ __align__(256) __half g_yUl[8192ull * 2048];       // lo (y half only)
__device__ __align__(256) __half g_Sh[4ull * 2048 * 2048];    // P hi
__device__ __align__(256) __half g_Ut[4ull * 1024 * 2048];    // U^T per batch

// ---------------------------------------------------------------------------
__device__ __forceinline__ uint32_t s2u(const void* p) {
    uint32_t a;
    asm("{ .reg .u64 t; cvta.to.shared.u64 t, %1; cvt.u32.u64 %0, t; }"
        : "=r"(a) : "l"(p));
    return a;
}

__device__ __forceinline__ void cp16(uint32_t dst, const void* src) {
    asm volatile("cp.async.cg.shared.global [%0], [%1], 16;" :: "r"(dst), "l"(src));
}

__device__ __forceinline__ void ldm4(uint32_t* r, uint32_t addr) {
    asm volatile("ldmatrix.sync.aligned.m8n8.x4.shared.b16 {%0,%1,%2,%3}, [%4];"
        : "=r"(r[0]), "=r"(r[1]), "=r"(r[2]), "=r"(r[3]) : "r"(addr));
}

__device__ __forceinline__ void mma_f16(float* c, const uint32_t* a,
                                        uint32_t b0, uint32_t b1) {
    asm volatile(
        "mma.sync.aligned.m16n8k16.row.col.f32.f16.f16.f32 "
        "{%0,%1,%2,%3}, {%4,%5,%6,%7}, {%8,%9}, {%0,%1,%2,%3};"
        : "+f"(c[0]), "+f"(c[1]), "+f"(c[2]), "+f"(c[3])
        : "r"(a[0]), "r"(a[1]), "r"(a[2]), "r"(a[3]), "r"(b0), "r"(b1));
}

__device__ __forceinline__ void split1(float x, __half& h, __half& l) {
    h = __float2half_rn(x);
    l = __float2half_rn(x - __half2float(h));
}

// ---------------------------------------------------------------------------
// fp32 -> (hi, lo) fp16 split, vectorized.
__global__ void __launch_bounds__(256)
split_kernel(const float4* __restrict__ in,
             __half2* __restrict__ h, __half2* __restrict__ l, int n4)
{
    int i = blockIdx.x * blockDim.x + threadIdx.x;
    if (i < n4) {
        float4 v = in[i];
        __half hx, hy, hz, hw, lx, ly, lz, lw;
        split1(v.x, hx, lx); split1(v.y, hy, ly);
        split1(v.z, hz, lz); split1(v.w, hw, lw);
        h[2 * i]     = __halves2half2(hx, hy);
        h[2 * i + 1] = __halves2half2(hz, hw);
        l[2 * i]     = __halves2half2(lx, ly);
        l[2 * i + 1] = __halves2half2(lz, lw);
    }
}

// ---------------------------------------------------------------------------
// Fused fp32 1024x1024 transpose + fp16 split: dsth/dstl[c][r] = split(src[r][c])
__global__ void __launch_bounds__(256)
transpose_split(const float* __restrict__ src,
                __half* __restrict__ dsth, __half* __restrict__ dstl)
{
    __shared__ float t[32][33];
    int r0 = blockIdx.x * 32, c0 = blockIdx.y * 32;
    int tx = threadIdx.x, ty = threadIdx.y;   // 32 x 8
#pragma unroll
    for (int i = 0; i < 32; i += 8)
        t[ty + i][tx] = src[(size_t)(r0 + ty + i) * 1024 + c0 + tx];
    __syncthreads();
#pragma unroll
    for (int i = 0; i < 32; i += 8) {
        float v = t[tx][ty + i];
        __half h, l;
        split1(v, h, l);
        size_t idx = (size_t)(c0 + ty + i) * 1024 + r0 + tx;
        dsth[idx] = h;
        dstl[idx] = l;
    }
}

// ---------------------------------------------------------------------------
// Ut[b][o][m] = yU[b*2048 + m][1024 + o]  (fp16, U = right half of yU)
__global__ void __launch_bounds__(256)
transpose_u(const __half* __restrict__ yU, __half* __restrict__ Ut)
{
    __shared__ __half t[32][34];
    int b  = blockIdx.z;
    int m0 = blockIdx.x * 32;
    int o0 = blockIdx.y * 32;
    int tx = threadIdx.x, ty = threadIdx.y;   // 32 x 8
    const __half* s = yU + (size_t)b * 2048 * 2048 + 1024;
#pragma unroll
    for (int i = 0; i < 32; i += 8)
        t[ty + i][tx] = s[(size_t)(m0 + ty + i) * 2048 + o0 + tx];
    __syncthreads();
    __half* d = Ut + (size_t)b * 1024 * 2048;
#pragma unroll
    for (int i = 0; i < 32; i += 8)
        d[(size_t)(o0 + ty + i) * 2048 + m0 + tx] = t[tx][ty + i];
}

// ---------------------------------------------------------------------------
// Split NT tensor-core GEMM: C = alpha*A B^T (+bias);
// NT=3: Ah·Bh + Ah·Bl + Al·Bh, with runtime column split: CTAs with
//       blockIdx.x >= xsplit3 drop the Ah·Bl term (2-term) and the Cl store.
// NT=1: Ah·Bh only.
// Grid (N/BN, M/BM, batch); 256 threads = 8 warps (2m x 4n), 64x32 per warp.
// ---------------------------------------------------------------------------
template <int NT>
__global__ void __launch_bounds__(256, 2)
gemm_nt_split(const __half* __restrict__ Ah, const __half* __restrict__ Al,
              const __half* __restrict__ Bh, const __half* __restrict__ Bl,
              float* __restrict__ Cf,
              __half* __restrict__ Ch, __half* __restrict__ Cl,
              const float* __restrict__ bias,
              int lda, int ldb, int ldc, int K, float alpha,
              long long sA, long long sB, long long sC, int xsplit3)
{
    extern __shared__ char smem[];
    constexpr uint32_t NTILES = (NT == 3) ? 4u : 2u;
    constexpr uint32_t STB   = NTILES * TILE_B;
    constexpr uint32_t O_BH  = (NT == 3) ? 2u * TILE_B : TILE_B;

    const bool three = (NT == 3) && ((int)blockIdx.x < xsplit3);

    const long long offA = (long long)blockIdx.z * sA;
    const long long offB = (long long)blockIdx.z * sB;
    const long long offC = (long long)blockIdx.z * sC;
    Ah += offA; if (NT == 3) Al += offA;
    Bh += offB; if (NT == 3) Bl += offB;

    const int tid  = threadIdx.x;
    const int wid  = tid >> 5, lane = tid & 31;
    const int wm   = wid & 1,  wn   = wid >> 1;
    const int g    = lane >> 2, t   = lane & 3;
    const int row0 = blockIdx.y * BM;
    const int col0 = blockIdx.x * BN;

    const uint32_t smem_u = s2u(smem);

    const __half* Abh = Ah + (size_t)row0 * lda;
    const __half* Abl = (NT == 3) ? (Al + (size_t)row0 * lda) : nullptr;
    const __half* Bbh = Bh + (size_t)col0 * ldb;
    const __half* Bbl = (NT == 3) ? (Bl + (size_t)col0 * ldb) : nullptr;

    float acc[4][4][4];
#pragma unroll
    for (int i = 0; i < 4; i++)
#pragma unroll
        for (int j = 0; j < 4; j++)
#pragma unroll
            for (int r = 0; r < 4; r++)
                acc[i][j][r] = 0.0f;

    const int nk = K / BK;

    const int lr = tid >> 2;
    const int lc = tid & 3;

    auto load_tile = [&](int kb, int s) {
        const uint32_t st = smem_u + (uint32_t)s * STB;
        const int kc = kb * BK + lc * 8;
#pragma unroll
        for (int hh = 0; hh < 2; hh++) {
            const int r = lr + hh * 64;
            const uint32_t phys = (uint32_t)(lc ^ ((r >> 1) & 3));
            const uint32_t off  = (uint32_t)(r * 64) + phys * 16u;
            cp16(st + off, Abh + (size_t)r * lda + kc);
            if (NT == 3)
                cp16(st + TILE_B + off, Abl + (size_t)r * lda + kc);
            cp16(st + O_BH + off, Bbh + (size_t)r * ldb + kc);
            if (NT == 3 && three)
                cp16(st + 3 * TILE_B + off, Bbl + (size_t)r * ldb + kc);
        }
    };

    load_tile(0, 0);
    asm volatile("cp.async.commit_group;");
    load_tile(1, 1);
    asm volatile("cp.async.commit_group;");

    const int lrow  = lane & 15;
    const int khalf = lane >> 4;

    int cur = 0;
    for (int kb = 0; kb < nk; kb++) {
        if (kb + 1 < nk) asm volatile("cp.async.wait_group 1;");
        else             asm volatile("cp.async.wait_group 0;");
        __syncthreads();

        const uint32_t st = smem_u + (uint32_t)cur * STB;

#pragma unroll
        for (int ks = 0; ks < 2; ks++) {
            uint32_t bh[2][4], bl[2][4], af[4][4];
#pragma unroll
            for (int jp = 0; jp < 2; jp++) {
                const int row = wn * 32 + jp * 16 + lrow;
                const uint32_t phys = (uint32_t)((ks * 2 + khalf) ^ ((row >> 1) & 3));
                const uint32_t bd = st + O_BH + (uint32_t)(row * 64) + phys * 16u;
                ldm4(bh[jp], bd);
                if (NT == 3 && three) ldm4(bl[jp], bd + TILE_B);
            }
#pragma unroll
            for (int i = 0; i < 4; i++) {
                const int row = wm * 64 + i * 16 + lrow;
                const uint32_t phys = (uint32_t)((ks * 2 + khalf) ^ ((row >> 1) & 3));
                ldm4(af[i], st + (uint32_t)(row * 64) + phys * 16u);
            }
#pragma unroll
            for (int i = 0; i < 4; i++)
#pragma unroll
                for (int j = 0; j < 4; j++) {
                    const int jp = j >> 1, sjj = j & 1;
                    mma_f16(acc[i][j], af[i], bh[jp][sjj], bh[jp][sjj + 2]);
                }
            if (NT == 3 && three) {
#pragma unroll
                for (int i = 0; i < 4; i++)
#pragma unroll
                    for (int j = 0; j < 4; j++) {
                        const int jp = j >> 1, sjj = j & 1;
                        mma_f16(acc[i][j], af[i], bl[jp][sjj], bl[jp][sjj + 2]);
                    }
            }
            if (NT == 3) {
#pragma unroll
                for (int i = 0; i < 4; i++) {
                    const int row = wm * 64 + i * 16 + lrow;
                    const uint32_t phys = (uint32_t)((ks * 2 + khalf) ^ ((row >> 1) & 3));
                    ldm4(af[i], st + TILE_B + (uint32_t)(row * 64) + phys * 16u);
                }
#pragma unroll
                for (int i = 0; i < 4; i++)
#pragma unroll
                    for (int j = 0; j < 4; j++) {
                        const int jp = j >> 1, sjj = j & 1;
                        mma_f16(acc[i][j], af[i], bh[jp][sjj], bh[jp][sjj + 2]);
                    }
            }
        }

        if (kb + 2 < nk) {
            const int ls = (cur + 2 >= 3) ? cur - 1 : cur + 2;
            load_tile(kb + 2, ls);
            asm volatile("cp.async.commit_group;");
        }
        cur = (cur + 1 == 3) ? 0 : cur + 1;
    }

    // ---- epilogue
    const bool wantCl = (Cl != nullptr) && (NT != 3 || three);
#pragma unroll
    for (int i = 0; i < 4; i++) {
        const int r = row0 + wm * 64 + i * 16 + g;
#pragma unroll
        for (int j = 0; j < 4; j++) {
            const int c = col0 + wn * 32 + j * 8 + 2 * t;
            float v[4];
            v[0] = alpha * acc[i][j][0];
            v[1] = alpha * acc[i][j][1];
            v[2] = alpha * acc[i][j][2];
            v[3] = alpha * acc[i][j][3];
            if (bias) {
                float bx = bias[c], by = bias[c + 1];
                v[0] += bx; v[1] += by; v[2] += bx; v[3] += by;
            }
            if (Cf) {
                *(float2*)(Cf + offC + (size_t)r * ldc + c)       = make_float2(v[0], v[1]);
                *(float2*)(Cf + offC + (size_t)(r + 8) * ldc + c) = make_float2(v[2], v[3]);
            }
            if (Ch) {
                __half h0, l0, h1, l1, h2, l2, h3, l3;
                split1(v[0], h0, l0); split1(v[1], h1, l1);
                split1(v[2], h2, l2); split1(v[3], h3, l3);
                *(__half2*)(Ch + offC + (size_t)r * ldc + c)       = __halves2half2(h0, h1);
                *(__half2*)(Ch + offC + (size_t)(r + 8) * ldc + c) = __halves2half2(h2, h3);
                if (wantCl) {
                    *(__half2*)(Cl + offC + (size_t)r * ldc + c)       = __halves2half2(l0, l1);
                    *(__half2*)(Cl + offC + (size_t)(r + 8) * ldc + c) = __halves2half2(l2, l3);
                }
            }
        }
    }
}

// ---------------------------------------------------------------------------
// Row softmax over 2048-wide rows (vectorized); writes fp16 probs (hi only).
__global__ void __launch_bounds__(256)
softmax_fp16(const float4* __restrict__ S4, __half2* __restrict__ Sh2)
{
    const size_t b4 = (size_t)blockIdx.x * 512;
    const int tid = threadIdx.x;

    float4 va = S4[b4 + tid];
    float4 vb = S4[b4 + tid + 256];

    float m = fmaxf(fmaxf(fmaxf(va.x, va.y), fmaxf(va.z, va.w)),
                    fmaxf(fmaxf(vb.x, vb.y), fmaxf(vb.z, vb.w)));

    __shared__ float red[8];
#pragma unroll
    for (int o = 16; o; o >>= 1) m = fmaxf(m, __shfl_xor_sync(0xffffffffu, m, o));
    if ((tid & 31) == 0) red[tid >> 5] = m;
    __syncthreads();
    m = red[0];
#pragma unroll
    for (int i = 1; i < 8; i++) m = fmaxf(m, red[i]);
    __syncthreads();

    va.x = __expf(va.x - m); va.y = __expf(va.y - m);
    va.z = __expf(va.z - m); va.w = __expf(va.w - m);
    vb.x = __expf(vb.x - m); vb.y = __expf(vb.y - m);
    vb.z = __expf(vb.z - m); vb.w = __expf(vb.w - m);
    float s = va.x + va.y + va.z + va.w + vb.x + vb.y + vb.z + vb.w;

#pragma unroll
    for (int o = 16; o; o >>= 1) s += __shfl_xor_sync(0xffffffffu, s, o);
    if ((tid & 31) == 0) red[tid >> 5] = s;
    __syncthreads();
    s = 0.0f;
#pragma unroll
    for (int i = 0; i < 8; i++) s += red[i];

    const float inv = 1.0f / s;
    const size_t h2base = (size_t)blockIdx.x * 1024;

    Sh2[h2base + 2 * tid] =
        __halves2half2(__float2half_rn(va.x * inv), __float2half_rn(va.y * inv));
    Sh2[h2base + 2 * tid + 1] =
        __halves2half2(__float2half_rn(va.z * inv), __float2half_rn(va.w * inv));
    Sh2[h2base + 2 * (tid + 256)] =
        __halves2half2(__float2half_rn(vb.x * inv), __float2half_rn(vb.y * inv));
    Sh2[h2base + 2 * (tid + 256) + 1] =
        __halves2half2(__float2half_rn(vb.z * inv), __float2half_rn(vb.w * inv));
}

// ---------------------------------------------------------------------------
extern "C" void kernel_launch(void* const* d_in, const int* in_sizes, int n_in,
                              void* d_out, int out_size)
{
    (void)in_sizes; (void)n_in; (void)out_size;
    const float* x     = (const float*)d_in[0];   // [4,2048,1024]
    const float* w_qkv = (const float*)d_in[1];   // [3072,1024]
    const float* w_out = (const float*)d_in[2];   // [1024,1024]
    const float* b_out = (const float*)d_in[3];   // [1024]
    float* out = (float*)d_out;                   // [4,2048,1024]

    float* S;
    __half *xh, *xl, *bAh, *bAl, *bBh, *bBl, *Wch, *Wcl, *yUh, *yUl, *Sh, *Ut;
    cudaGetSymbolAddress((void**)&S,    g_S);
    cudaGetSymbolAddress((void**)&xh,   g_xh);   cudaGetSymbolAddress((void**)&xl,   g_xl);
    cudaGetSymbolAddress((void**)&bAh,  g_bAh);  cudaGetSymbolAddress((void**)&bAl,  g_bAl);
    cudaGetSymbolAddress((void**)&bBh,  g_bBh);  cudaGetSymbolAddress((void**)&bBl,  g_bBl);
    cudaGetSymbolAddress((void**)&Wch,  g_Wch);  cudaGetSymbolAddress((void**)&Wcl,  g_Wcl);
    cudaGetSymbolAddress((void**)&yUh,  g_yUh);  cudaGetSymbolAddress((void**)&yUl,  g_yUl);
    cudaGetSymbolAddress((void**)&Sh,   g_Sh);
    cudaGetSymbolAddress((void**)&Ut,   g_Ut);

    const int SM3 = 3 * 4 * TILE_B;   // 98304
    const int SM1 = 3 * 2 * TILE_B;   // 49152
    cudaFuncSetAttribute(gemm_nt_split<3>,
                         cudaFuncAttributeMaxDynamicSharedMemorySize, SM3);
    cudaFuncSetAttribute(gemm_nt_split<1>,
                         cudaFuncAttributeMaxDynamicSharedMemorySize, SM1);

    const int ALL3 = 1 << 30;

    // 0) split x; build packed weight operands (fused transpose+split)
    {
        int n4 = 8192 * 1024 / 4;
        split_kernel<<<(n4 + 255) / 256, 256>>>((const float4*)x,
            (__half2*)xh, (__half2*)xl, n4);
    }
    // bA = [Wk^T ; Wo],  bB = [Wq^T ; Wv^T]
    transpose_split<<<dim3(32, 32), dim3(32, 8)>>>(w_qkv + 1024ll * 1024, bAh, bAl);
    {
        int n4 = 1024 * 1024 / 4;   // Wo: no transpose
        split_kernel<<<(n4 + 255) / 256, 256>>>((const float4*)w_out,
            (__half2*)(bAh + 1024ll * 1024), (__half2*)(bAl + 1024ll * 1024), n4);
    }
    transpose_split<<<dim3(32, 32), dim3(32, 8)>>>(w_qkv, bBh, bBl);
    transpose_split<<<dim3(32, 32), dim3(32, 8)>>>(w_qkv + 2048ll * 1024,
                                                   bBh + 1024ll * 1024,
                                                   bBl + 1024ll * 1024);

    // 1) weight products (batched z=2): Wc[0]=W~^T, Wc[1]=G~^T (3-term)
    gemm_nt_split<3><<<dim3(8, 8, 2), 256, SM3>>>(
        bAh, bAl, bBh, bBl, nullptr, Wch, Wcl, nullptr,
        1024, 1024, 1024, 1024, 1.0f,
        1024ll * 1024, 1024ll * 1024, 1024ll * 1024, ALL3);

    // 2) [y|U] = x @ Wc^T : M=8192, N=2048, K=1024 -- ONE launch;
    //    blockIdx.x < 8 (y half) 3-term + lo store; >= 8 (U half) 2-term, hi only
    gemm_nt_split<3><<<dim3(16, 64, 1), 256, SM3>>>(
        xh, xl, Wch, Wcl, nullptr, yUh, yUl, nullptr,
        1024, 1024, 2048, 1024, 1.0f, 0, 0, 0, 8);

    // 3) S[b] = y[b] @ x[b]^T * 0.125 : fp32 out (3-term)
    gemm_nt_split<3><<<dim3(16, 16, 4), 256, SM3>>>(
        yUh, yUl, xh, xl, S, nullptr, nullptr, nullptr,
        2048, 1024, 2048, 1024, 0.125f,
        2048ll * 2048, 2048ll * 1024, 2048ll * 2048, ALL3);

    // 4) softmax -> fp16 probs (hi only)
    softmax_fp16<<<4 * 2048, 256>>>((const float4*)S, (__half2*)Sh);

    // 5) Ut[b] = U[b]^T
    transpose_u<<<dim3(64, 32, 4), dim3(32, 8)>>>(yUh, Ut);

    // 6) out = Ph @ U + b_out : M=2048, N=1024, K=2048 (1-term)
    gemm_nt_split<1><<<dim3(8, 16, 4), 256, SM1>>>(
        Sh, nullptr, Ut, nullptr, out, nullptr, nullptr, b_out,
        2048, 2048, 1024, 2048, 1.0f,
        2048ll * 2048, 1024ll * 2048, 2048ll * 1024, 0);
}